// round 1
// baseline (speedup 1.0000x reference)
#include <cuda_runtime.h>

// GraphAggregation: out[b][d] = mean over 196 nodes of in[b][n*4 + d]
// in:  (B, 784) float32   out: (B, 4) float32
// One warp per row; lane l loads float4 node-vectors k*32+l (coalesced 512B
// per warp per iteration), butterfly-reduce, lane 0 writes one float4.

__global__ void __launch_bounds__(256, 8)
graph_agg_kernel(const float4* __restrict__ in, float4* __restrict__ out, int B)
{
    const int warp = (int)((blockIdx.x * (unsigned)blockDim.x + threadIdx.x) >> 5);
    const int lane = threadIdx.x & 31;
    if (warp >= B) return;

    const float4* row = in + (size_t)warp * 196;

    float ax = 0.f, ay = 0.f, az = 0.f, aw = 0.f;

    // 196 = 6*32 + 4
    #pragma unroll
    for (int k = 0; k < 6; ++k) {
        float4 v = __ldg(row + k * 32 + lane);
        ax += v.x; ay += v.y; az += v.z; aw += v.w;
    }
    if (lane < 4) {
        float4 v = __ldg(row + 192 + lane);
        ax += v.x; ay += v.y; az += v.z; aw += v.w;
    }

    // warp butterfly reduction of the 4 components
    #pragma unroll
    for (int off = 16; off > 0; off >>= 1) {
        ax += __shfl_xor_sync(0xffffffffu, ax, off);
        ay += __shfl_xor_sync(0xffffffffu, ay, off);
        az += __shfl_xor_sync(0xffffffffu, az, off);
        aw += __shfl_xor_sync(0xffffffffu, aw, off);
    }

    if (lane == 0) {
        const float s = 1.0f / 196.0f;
        out[warp] = make_float4(ax * s, ay * s, az * s, aw * s);
    }
}

extern "C" void kernel_launch(void* const* d_in, const int* in_sizes, int n_in,
                              void* d_out, int out_size)
{
    const float4* in  = (const float4*)d_in[0];
    float4*       out = (float4*)d_out;
    const int B = in_sizes[0] / 784;          // 131072

    const int threads = 256;                   // 8 warps/block
    const int rows_per_block = threads / 32;
    const int blocks = (B + rows_per_block - 1) / rows_per_block;

    graph_agg_kernel<<<blocks, threads>>>(in, out, B);
}